// round 13
// baseline (speedup 1.0000x reference)
#include <cuda_runtime.h>
#include <cuda_fp16.h>
#include <math.h>
#include <stdint.h>

#define BATCH 4
#define SEQ   2048
#define EMB   1024
#define HEADS 16
#define HDIM  64
#define MROWS (BATCH*SEQ)   // 8192

typedef __half fp16;

// ---------------- scratch ------------------------------------------------------
__device__ fp16 g_A1[MROWS*EMB];    // query cvt / ctx output
__device__ fp16 g_A2[MROWS*EMB];    // key cvt
__device__ fp16 g_A3[MROWS*EMB];    // value cvt
__device__ fp16 g_W1[EMB*EMB];      // Wq
__device__ fp16 g_W2[EMB*EMB];      // Wk
__device__ fp16 g_W3[EMB*EMB];      // Wv
__device__ fp16 g_W4[EMB*EMB];      // Wo
__device__ fp16 g_Qf[MROWS*EMB];    // Q fp16 (rscale folded), [b,s,h,d]
__device__ fp16 g_Kf[MROWS*EMB];    // K fp16 [b,s,h,d]
__device__ fp16 g_Vf[MROWS*EMB];    // V fp16 [b,s,h,d]

// ---------------- helpers ------------------------------------------------------
__device__ __forceinline__ uint32_t smem_u32(const void* p) {
    return (uint32_t)__cvta_generic_to_shared(p);
}
__device__ __forceinline__ void cp_async16(uint32_t dst, const void* src) {
    asm volatile("cp.async.cg.shared.global [%0], [%1], 16;"
                 :: "r"(dst), "l"(src));
}
#define CP_COMMIT() asm volatile("cp.async.commit_group;" ::: "memory")
#define CP_WAIT2()  asm volatile("cp.async.wait_group 2;" ::: "memory")
#define CP_WAIT1()  asm volatile("cp.async.wait_group 1;" ::: "memory")
#define CP_WAIT0()  asm volatile("cp.async.wait_group 0;" ::: "memory")

__device__ __forceinline__ void ldsm_x4(uint32_t& r0, uint32_t& r1, uint32_t& r2,
                                        uint32_t& r3, uint32_t addr) {
    asm volatile("ldmatrix.sync.aligned.m8n8.x4.shared.b16 {%0,%1,%2,%3}, [%4];"
                 : "=r"(r0), "=r"(r1), "=r"(r2), "=r"(r3) : "r"(addr));
}
__device__ __forceinline__ void ldsm_x2(uint32_t& r0, uint32_t& r1, uint32_t addr) {
    asm volatile("ldmatrix.sync.aligned.m8n8.x2.shared.b16 {%0,%1}, [%2];"
                 : "=r"(r0), "=r"(r1) : "r"(addr));
}
__device__ __forceinline__ void ldsm_x2t(uint32_t& r0, uint32_t& r1, uint32_t addr) {
    asm volatile("ldmatrix.sync.aligned.m8n8.x2.trans.shared.b16 {%0,%1}, [%2];"
                 : "=r"(r0), "=r"(r1) : "r"(addr));
}
__device__ __forceinline__ void mma_f16(float (&c)[4], const uint32_t (&a)[4],
                                        const uint32_t (&b)[2]) {
    asm volatile(
        "mma.sync.aligned.m16n8k16.row.col.f32.f16.f16.f32 "
        "{%0,%1,%2,%3}, {%4,%5,%6,%7}, {%8,%9}, {%0,%1,%2,%3};"
        : "+f"(c[0]), "+f"(c[1]), "+f"(c[2]), "+f"(c[3])
        : "r"(a[0]), "r"(a[1]), "r"(a[2]), "r"(a[3]), "r"(b[0]), "r"(b[1]));
}
__device__ __forceinline__ uint32_t pack2h(fp16 a, fp16 b) {
    __half2 t = __halves2half2(a, b);
    return *(uint32_t*)&t;
}
__device__ __forceinline__ float fast_exp(float x) {
    const float L2E   = 1.4426950408889634f;
    const float MAGIC = 12582912.0f;           // 1.5 * 2^23
    float t = x * L2E;
    float z = t + MAGIC;
    int   i = __float_as_int(z);
    float k = z - MAGIC;
    float f = t - k;
    float p =         1.3333558146e-3f;
    p = fmaf(p, f,    9.6181291076e-3f);
    p = fmaf(p, f,    5.5504108665e-2f);
    p = fmaf(p, f,    2.4022650696e-1f);
    p = fmaf(p, f,    6.9314718056e-1f);
    p = fmaf(p, f,    1.0f);
    float s = __int_as_float((i - 0x4B400000 + 127) << 23);
    return p * s;
}

// ---------------- cvt_all: all 7 fp32->fp16 conversions in one launch -------------
#define N4_IN (MROWS*EMB/4)    // 2097152
#define N4_W  (EMB*EMB/4)      // 262144
#define CVT_TOTAL (3*N4_IN + 4*N4_W)

__global__ __launch_bounds__(256)
void cvt_all(const float* __restrict__ q, const float* __restrict__ k,
             const float* __restrict__ v,
             const float* __restrict__ wq, const float* __restrict__ wk,
             const float* __restrict__ wv, const float* __restrict__ wo,
             fp16* __restrict__ A1, fp16* __restrict__ A2, fp16* __restrict__ A3,
             fp16* __restrict__ W1, fp16* __restrict__ W2, fp16* __restrict__ W3,
             fp16* __restrict__ W4) {
    int i = blockIdx.x * 256 + threadIdx.x;
    if (i >= CVT_TOTAL) return;
    const float* src;
    fp16* dst;
    if (i < 3 * N4_IN) {
        int job = i / N4_IN;
        i -= job * N4_IN;
        src = (job == 0) ? q : (job == 1) ? k : v;
        dst = (job == 0) ? A1 : (job == 1) ? A2 : A3;
    } else {
        int j = i - 3 * N4_IN;
        int job = j / N4_W;
        i = j - job * N4_W;
        src = (job == 0) ? wq : (job == 1) ? wk : (job == 2) ? wv : wo;
        dst = (job == 0) ? W1 : (job == 1) ? W2 : (job == 2) ? W3 : W4;
    }
    float4 vv = ((const float4*)src)[i];
    uint2 o;
    o.x = pack2h(__float2half_rn(vv.x), __float2half_rn(vv.y));
    o.y = pack2h(__float2half_rn(vv.z), __float2half_rn(vv.w));
    ((uint2*)dst)[i] = o;
}

// ---------------- GEMM body (fp16 mma, BK=64, cp.async 3-stage, distance 2) -------
#define GROW 72               // smem row stride (halves): 64 + 8 pad
#define PL   (128*GROW)       // halves per plane (9216)
#define GSTG (2*PL)           // halves per stage (A + W)
#define GEMM_SMEM (3*GSTG*2)  // bytes = 110592

__device__ __forceinline__
void gemm_stage_load(const fp16* __restrict__ A, const fp16* __restrict__ W,
                     uint32_t smb, int stage, int m0, int n0, int k0, int K,
                     int tid) {
#pragma unroll
    for (int i = 0; i < 8; i++) {
        int idx = tid + i * 256;
        int pl = idx >> 10, rem = idx & 1023;
        int row = rem >> 3, c8 = (rem & 7) * 8;
        const fp16* src = pl ? W : A;
        int rb = pl ? n0 : m0;
        cp_async16(smb + (stage * GSTG + pl * PL + row * GROW + c8) * 2,
                   src + (size_t)(rb + row) * K + k0 + c8);
    }
    CP_COMMIT();
}

__device__ __forceinline__
void gemm_body(const fp16* __restrict__ A, const fp16* __restrict__ W,
               const float* __restrict__ bias,
               float* __restrict__ Cf, fp16* __restrict__ Ch,
               float oscale, int M, int N, int K, char* smraw) {
    const uint32_t smb = smem_u32(smraw);

    const int tid  = threadIdx.x;
    const int lane = tid & 31;
    const int wid  = tid >> 5;
    const int wm   = wid >> 2;
    const int wn   = wid & 3;
    const int m0 = blockIdx.y * 128;
    const int n0 = blockIdx.x * 128;

    float acc[4][4][4];
#pragma unroll
    for (int i = 0; i < 4; i++)
#pragma unroll
        for (int j = 0; j < 4; j++)
#pragma unroll
            for (int qq = 0; qq < 4; qq++) acc[i][j][qq] = 0.f;

    // prologue: prefetch chunks 0 and 1
    gemm_stage_load(A, W, smb, 0, m0, n0, 0, K, tid);
    gemm_stage_load(A, W, smb, 1, m0, n0, 64, K, tid);

    const int NCH = K / 64;
    int stage = 0;
    for (int ch = 0; ch < NCH; ch++) {
        if (ch + 2 < NCH) {
            gemm_stage_load(A, W, smb, (stage + 2) % 3, m0, n0, (ch + 2) * 64, K, tid);
            CP_WAIT2();
        } else if (ch + 1 < NCH) {
            CP_WAIT1();
        } else {
            CP_WAIT0();
        }
        __syncthreads();

        const uint32_t bA = stage * GSTG;
#pragma unroll
        for (int kk = 0; kk < 4; kk++) {
            uint32_t af[4][4], bf[2][4];
#pragma unroll
            for (int mt = 0; mt < 4; mt++) {
                uint32_t off = (bA + (wm * 64 + mt * 16 + (lane & 15)) * GROW
                                + kk * 16 + (lane >> 4) * 8) * 2;
                ldsm_x4(af[mt][0], af[mt][1], af[mt][2], af[mt][3], smb + off);
            }
#pragma unroll
            for (int ntp = 0; ntp < 2; ntp++) {
                uint32_t off = (bA + PL + (wn * 32 + ntp * 16 + (lane & 15)) * GROW
                                + kk * 16 + (lane >> 4) * 8) * 2;
                ldsm_x4(bf[ntp][0], bf[ntp][1], bf[ntp][2], bf[ntp][3], smb + off);
            }
#pragma unroll
            for (int mt = 0; mt < 4; mt++)
#pragma unroll
                for (int nt = 0; nt < 4; nt++) {
                    uint32_t bb[2] = {bf[nt >> 1][nt & 1], bf[nt >> 1][(nt & 1) + 2]};
                    mma_f16(acc[mt][nt], af[mt], bb);
                }
        }
        __syncthreads();
        stage = (stage + 1) % 3;
    }

    // epilogue
#pragma unroll
    for (int nt = 0; nt < 4; nt++) {
        int n = n0 + wn * 32 + nt * 8 + (lane & 3) * 2;
        float b0 = bias[n], b1 = bias[n + 1];
#pragma unroll
        for (int mt = 0; mt < 4; mt++) {
            int m = m0 + wm * 64 + mt * 16 + (lane >> 2);
            float v00 = (acc[mt][nt][0] + b0) * oscale;
            float v01 = (acc[mt][nt][1] + b1) * oscale;
            float v10 = (acc[mt][nt][2] + b0) * oscale;
            float v11 = (acc[mt][nt][3] + b1) * oscale;
            size_t i0 = (size_t)m * N + n;
            size_t i1 = (size_t)(m + 8) * N + n;
            if (Cf) {
                *(float2*)&Cf[i0] = make_float2(v00, v01);
                *(float2*)&Cf[i1] = make_float2(v10, v11);
            }
            if (Ch) {
                *(uint32_t*)&Ch[i0] = pack2h(__float2half_rn(v00), __float2half_rn(v01));
                *(uint32_t*)&Ch[i1] = pack2h(__float2half_rn(v10), __float2half_rn(v11));
            }
        }
    }
}

// fused Q/K/V projections: blockIdx.z selects the job
__global__ __launch_bounds__(256, 2)
void gemm3_hmma(const fp16* __restrict__ A1, const fp16* __restrict__ W1,
                const float* __restrict__ bq, fp16* __restrict__ Qf,
                const fp16* __restrict__ A2, const fp16* __restrict__ W2,
                const float* __restrict__ bk, fp16* __restrict__ Kf,
                const fp16* __restrict__ A3, const fp16* __restrict__ W3,
                const float* __restrict__ bv, fp16* __restrict__ Vf) {
    extern __shared__ char sm[];
    int z = blockIdx.z;
    if (z == 0)
        gemm_body(A1, W1, bq, nullptr, Qf, 0.125f, MROWS, EMB, EMB, sm);
    else if (z == 1)
        gemm_body(A2, W2, bk, nullptr, Kf, 1.f, MROWS, EMB, EMB, sm);
    else
        gemm_body(A3, W3, bv, nullptr, Vf, 1.f, MROWS, EMB, EMB, sm);
}

// single GEMM (output projection)
__global__ __launch_bounds__(256, 2)
void gemm_hmma(const fp16* __restrict__ A, const fp16* __restrict__ W,
               const float* __restrict__ bias, float* __restrict__ Cf,
               float oscale, int M, int N, int K) {
    extern __shared__ char sm[];
    gemm_body(A, W, bias, Cf, nullptr, oscale, M, N, K, sm);
}

// ---------------- fused single-pass attention ---------------------------------------
#define QROWS 32
#define KCH   128
#define SROW  2056
#define KROWS 72
#define QROW  72
#define NTHR  512
#define A_S    0
#define S_BYTES (32*SROW*2)
#define A_U    S_BYTES
#define KPL    (KCH*KROWS*2)
#define STGB   (2*KPL)
#define A_QS   (A_U + 2*STGB)
#define A_RSUM (A_QS + 32*QROW*2)
#define ATTN_SMEM (A_RSUM + 256)

__global__ __launch_bounds__(NTHR, 1)
void attn_fused(const fp16* __restrict__ Qf, const fp16* __restrict__ Kf,
                const fp16* __restrict__ Vf,
                fp16* __restrict__ ctx, float* __restrict__ meanOut, int writeMean) {
    extern __shared__ char smem_raw[];
    fp16*  S      = (fp16*)(smem_raw + A_S);
    float* Sred   = (float*)(smem_raw + A_S);
    fp16*  Qs     = (fp16*)(smem_raw + A_QS);
    float* rowsum = (float*)(smem_raw + A_RSUM);

    const int b    = blockIdx.y;
    const int q0   = blockIdx.x * QROWS;
    const int tid  = threadIdx.x;
    const int lane = tid & 31;
    const int wid  = tid >> 5;
    const int rg   = wid >> 3;
    const int ks   = wid & 7;
    const float invH = 1.0f / HEADS;

    const uint32_t smb  = smem_u32(smem_raw);
    const uint32_t U_b  = smb + A_U;
    const uint32_t Qs_b = smb + A_QS;

    const fp16* KbB = Kf + (size_t)(b * SEQ) * EMB;
    const fp16* VbB = Vf + (size_t)(b * SEQ) * EMB;

    for (int h = 0; h < HEADS; h++) {
        if (tid < 32) rowsum[tid] = 0.f;
        {
            int row = tid >> 4, c4 = (tid & 15) * 4;
            size_t g = (size_t)(b * SEQ + q0 + row) * EMB + h * HDIM + c4;
            *(uint2*)&Qs[row * QROW + c4] = *(const uint2*)&Qf[g];
        }
        if (h == 0) {
#pragma unroll
            for (int i = 0; i < 4; i++) {
                int idx = tid + i * NTHR;
                int pl = idx >> 10, rem = idx & 1023;
                int row = rem >> 3, q8 = (rem & 7) * 8;
                const fp16* src = pl ? (VbB + h * HDIM) : (KbB + h * HDIM);
                cp_async16(U_b + pl * KPL + (row * KROWS + q8) * 2,
                           src + (size_t)row * EMB + q8);
            }
            CP_COMMIT();
        }
        __syncthreads();

        uint32_t Af[4][4];
#pragma unroll
        for (int ds = 0; ds < 4; ds++) {
            uint32_t off = ((rg * 16 + (lane & 15)) * QROW
                            + ds * 16 + (lane >> 4) * 8) * 2;
            ldsm_x4(Af[ds][0], Af[ds][1], Af[ds][2], Af[ds][3], Qs_b + off);
        }

        float out[8][4];
#pragma unroll
        for (int n8 = 0; n8 < 8; n8++)
#pragma unroll
            for (int qq = 0; qq < 4; qq++) out[n8][qq] = 0.f;
        float rs0 = 0.f, rs1 = 0.f;

        const fp16* Kb0 = KbB + h * HDIM;
        const fp16* Vb0 = VbB + h * HDIM;
        const int l = lane & 15;

        for (int ci = 0; ci < SEQ / KCH; ci++) {
            const int buf = ci & 1;
            if (ci + 1 < SEQ / KCH) {
                const int nb = buf ^ 1;
                const int kc2 = (ci + 1) * KCH;
#pragma unroll
                for (int i = 0; i < 4; i++) {
                    int idx = tid + i * NTHR;
                    int pl = idx >> 10, rem = idx & 1023;
                    int row = rem >> 3, q8 = (rem & 7) * 8;
                    const fp16* src = pl ? Vb0 : Kb0;
                    cp_async16(U_b + nb * STGB + pl * KPL + (row * KROWS + q8) * 2,
                               src + (size_t)(kc2 + row) * EMB + q8);
                }
                CP_COMMIT();
                CP_WAIT1();
            } else {
                CP_WAIT0();
            }
            __syncthreads();

            const uint32_t kb = U_b + buf * STGB;
            const uint32_t vb = kb + KPL;

            // ---- hoist V fragments (independent of scores/exp)
            uint32_t vfr[8][2];
#pragma unroll
            for (int n8 = 0; n8 < 8; n8++) {
                uint32_t boff = ((ks * 16 + l) * KROWS + n8 * 8) * 2;
                ldsm_x2t(vfr[n8][0], vfr[n8][1], vb + boff);
            }

            // ---- scores: two accumulator chains interleaved over ds
            float c0[4] = {0.f, 0.f, 0.f, 0.f};
            float c1[4] = {0.f, 0.f, 0.f, 0.f};
#pragma unroll
            for (int ds = 0; ds < 4; ds++) {
                uint32_t b0off = ((ks * 16 + (l & 7)) * KROWS
                                  + ds * 16 + ((l >> 3) & 1) * 8) * 2;
                uint32_t b1off = ((ks * 16 + 8 + (l & 7)) * KROWS
                                  + ds * 16 + ((l >> 3) & 1) * 8) * 2;
                uint32_t k0[2], k1[2];
                ldsm_x2(k0[0], k0[1], kb + b0off);
                ldsm_x2(k1[0], k1[1], kb + b1off);
                mma_f16(c0, Af[ds], k0);
                mma_f16(c1, Af[ds], k1);
            }

            // ---- exp, rowsum, pack P a-fragment
            float e0 = fast_exp(c0[0]);
            float e1 = fast_exp(c0[1]);
            float e2 = fast_exp(c0[2]);
            float e3 = fast_exp(c0[3]);
            float e4 = fast_exp(c1[0]);
            float e5 = fast_exp(c1[1]);
            float e6 = fast_exp(c1[2]);
            float e7 = fast_exp(c1[3]);
            rs0 += (e0 + e1) + (e4 + e5);
            rs1 += (e2 + e3) + (e6 + e7);
            uint32_t pa[4];
            pa[0] = pack2h(__float2half_rn(e0), __float2half_rn(e1));
            pa[1] = pack2h(__float2half_rn(e2), __float2half_rn(e3));
            pa[2] = pack2h(__float2half_rn(e4), __float2half_rn(e5));
            pa[3] = pack2h(__float2half_rn(e6), __float2half_rn(e7));

            // ---- PV with pre-loaded V fragments
#pragma unroll
            for (int n8 = 0; n8 < 8; n8++)
                mma_f16(out[n8], pa, vfr[n8]);

            // ---- S stores (off critical path)
            {
                int row0 = rg * 16 + (lane >> 2);
                int col  = ci * KCH + ks * 16 + (lane & 3) * 2;
                *(uint32_t*)&S[row0 * SROW + col]           = pa[0];
                *(uint32_t*)&S[(row0 + 8) * SROW + col]     = pa[1];
                *(uint32_t*)&S[row0 * SROW + col + 8]       = pa[2];
                *(uint32_t*)&S[(row0 + 8) * SROW + col + 8] = pa[3];
            }
            __syncthreads();
        }

        if (h + 1 < HEADS) {
            const fp16* Kn = KbB + (h + 1) * HDIM;
            const fp16* Vn = VbB + (h + 1) * HDIM;
#pragma unroll
            for (int i = 0; i < 4; i++) {
                int idx = tid + i * NTHR;
                int pl = idx >> 10, rem = idx & 1023;
                int row = rem >> 3, q8 = (rem & 7) * 8;
                const fp16* src = pl ? Vn : Kn;
                cp_async16(U_b + pl * KPL + (row * KROWS + q8) * 2,
                           src + (size_t)row * EMB + q8);
            }
            CP_COMMIT();
        }

        rs0 += __shfl_xor_sync(0xffffffffu, rs0, 1);
        rs0 += __shfl_xor_sync(0xffffffffu, rs0, 2);
        rs1 += __shfl_xor_sync(0xffffffffu, rs1, 1);
        rs1 += __shfl_xor_sync(0xffffffffu, rs1, 2);
        if ((lane & 3) == 0) {
            int r = rg * 16 + (lane >> 2);
            atomicAdd(&rowsum[r], rs0);
            atomicAdd(&rowsum[r + 8], rs1);
        }
        __syncthreads();

        if (writeMean) {
#pragma unroll
            for (int rr = 0; rr < 2; rr++) {
                const int r = wid * 2 + rr;
                float fac = invH / rowsum[r];
                float* mrow = meanOut + ((size_t)b * SEQ + q0 + r) * SEQ;
#pragma unroll
                for (int it = 0; it < 8; it++) {
                    int base = it * 256 + lane * 8;
                    uint4 hv = *(uint4*)&S[r * SROW + base];
                    __half2* hp = (__half2*)&hv;
                    float e[8];
#pragma unroll
                    for (int p = 0; p < 4; p++) {
                        float2 f = __half22float2(hp[p]);
                        e[p * 2]     = f.x;
                        e[p * 2 + 1] = f.y;
                    }
                    if (h == 0) {
                        float4 m0 = make_float4(e[0] * fac, e[1] * fac,
                                                e[2] * fac, e[3] * fac);
                        float4 m1 = make_float4(e[4] * fac, e[5] * fac,
                                                e[6] * fac, e[7] * fac);
                        *(float4*)&mrow[base]     = m0;
                        *(float4*)&mrow[base + 4] = m1;
                    } else {
                        float4 m0 = *(const float4*)&mrow[base];
                        float4 m1 = *(const float4*)&mrow[base + 4];
                        m0.x = fmaf(e[0], fac, m0.x); m0.y = fmaf(e[1], fac, m0.y);
                        m0.z = fmaf(e[2], fac, m0.z); m0.w = fmaf(e[3], fac, m0.w);
                        m1.x = fmaf(e[4], fac, m1.x); m1.y = fmaf(e[5], fac, m1.y);
                        m1.z = fmaf(e[6], fac, m1.z); m1.w = fmaf(e[7], fac, m1.w);
                        *(float4*)&mrow[base]     = m0;
                        *(float4*)&mrow[base + 4] = m1;
                    }
                }
            }
        }
        __syncthreads();

        {
            float* dst = Sred + wid * 1024;
            int rl = lane >> 2, cl = (lane & 3) * 2;
#pragma unroll
            for (int n8 = 0; n8 < 8; n8++) {
                *(float2*)&dst[rl * 64 + n8 * 8 + cl]       =
                    make_float2(out[n8][0], out[n8][1]);
                *(float2*)&dst[(rl + 8) * 64 + n8 * 8 + cl] =
                    make_float2(out[n8][2], out[n8][3]);
            }
        }
        __syncthreads();

        {
            int row = tid >> 4;
            int col = (tid & 15) * 4;
            float s4[4] = {0.f, 0.f, 0.f, 0.f};
            int wbase = (row >> 4) * 8;
            int off   = (row & 15) * 64 + col;
#pragma unroll
            for (int w = 0; w < 8; w++) {
                const float* src = Sred + (wbase + w) * 1024 + off;
                s4[0] += src[0]; s4[1] += src[1];
                s4[2] += src[2]; s4[3] += src[3];
            }
            float inv = __fdividef(1.f, rowsum[row]);
            uint2 o;
            o.x = pack2h(__float2half_rn(s4[0] * inv), __float2half_rn(s4[1] * inv));
            o.y = pack2h(__float2half_rn(s4[2] * inv), __float2half_rn(s4[3] * inv));
            *(uint2*)&ctx[(size_t)(b * SEQ + q0 + row) * EMB + h * HDIM + col] = o;
        }
        __syncthreads();
    }
}

// ---------------- launch ------------------------------------------------------------
extern "C" void kernel_launch(void* const* d_in, const int* in_sizes, int n_in,
                              void* d_out, int out_size) {
    const float* query = (const float*)d_in[0];
    const float* key_  = (const float*)d_in[1];
    const float* value = (const float*)d_in[2];
    const float* Wq = (const float*)d_in[3];
    const float* bq = (const float*)d_in[4];
    const float* Wk = (const float*)d_in[5];
    const float* bk = (const float*)d_in[6];
    const float* Wv = (const float*)d_in[7];
    const float* bv = (const float*)d_in[8];
    const float* Wo = (const float*)d_in[9];
    const float* bo = (const float*)d_in[10];

    float* out = (float*)d_out;
    const size_t outElems  = (size_t)MROWS * EMB;
    const size_t meanElems = (size_t)BATCH * SEQ * SEQ;
    int writeMean = ((size_t)out_size >= outElems + meanElems) ? 1 : 0;
    float* meanOut = out + outElems;

    fp16 *A1, *A2, *A3, *W1, *W2, *W3, *W4, *Qfb, *Kfb, *Vfb;
    cudaGetSymbolAddress((void**)&A1,  g_A1);
    cudaGetSymbolAddress((void**)&A2,  g_A2);
    cudaGetSymbolAddress((void**)&A3,  g_A3);
    cudaGetSymbolAddress((void**)&W1,  g_W1);
    cudaGetSymbolAddress((void**)&W2,  g_W2);
    cudaGetSymbolAddress((void**)&W3,  g_W3);
    cudaGetSymbolAddress((void**)&W4,  g_W4);
    cudaGetSymbolAddress((void**)&Qfb, g_Qf);
    cudaGetSymbolAddress((void**)&Kfb, g_Kf);
    cudaGetSymbolAddress((void**)&Vfb, g_Vf);

    cudaFuncSetAttribute(gemm3_hmma, cudaFuncAttributeMaxDynamicSharedMemorySize,
                         GEMM_SMEM);
    cudaFuncSetAttribute(gemm_hmma, cudaFuncAttributeMaxDynamicSharedMemorySize,
                         GEMM_SMEM);
    cudaFuncSetAttribute(attn_fused, cudaFuncAttributeMaxDynamicSharedMemorySize,
                         ATTN_SMEM);

    // 1) all conversions (7 jobs, one launch)
    cvt_all<<<(CVT_TOTAL + 255) / 256, 256>>>(
        query, key_, value, Wq, Wk, Wv, Wo,
        A1, A2, A3, W1, W2, W3, W4);

    // 2) Q/K/V projections fused in one grid (z = job)
    gemm3_hmma<<<dim3(EMB / 128, MROWS / 128, 3), 256, GEMM_SMEM>>>(
        A1, W1, bq, Qfb,
        A2, W2, bk, Kfb,
        A3, W3, bv, Vfb);

    // 3) fused attention -> ctx fp16 into A1
    attn_fused<<<dim3(SEQ / QROWS, BATCH), NTHR, ATTN_SMEM>>>(
        Qfb, Kfb, Vfb, A1, meanOut, writeMean);

    // 4) output projection -> fp32 out
    gemm_hmma<<<dim3(EMB / 128, MROWS / 128), 256, GEMM_SMEM>>>(
        A1, W4, bo, out, 1.f, MROWS, EMB, EMB);
}

// round 16
// speedup vs baseline: 1.0577x; 1.0577x over previous
#include <cuda_runtime.h>
#include <cuda_fp16.h>
#include <math.h>
#include <stdint.h>

#define BATCH 4
#define SEQ   2048
#define EMB   1024
#define HEADS 16
#define HDIM  64
#define MROWS (BATCH*SEQ)   // 8192

typedef __half fp16;

// ---------------- scratch ------------------------------------------------------
__device__ fp16 g_A1[MROWS*EMB];    // query cvt / ctx output
__device__ fp16 g_A2[MROWS*EMB];    // key cvt
__device__ fp16 g_A3[MROWS*EMB];    // value cvt
__device__ fp16 g_W1[EMB*EMB];      // Wq
__device__ fp16 g_W2[EMB*EMB];      // Wk
__device__ fp16 g_W3[EMB*EMB];      // Wv
__device__ fp16 g_W4[EMB*EMB];      // Wo
__device__ fp16 g_Qf[MROWS*EMB];    // Q fp16 (rscale folded), [b,s,h,d]
__device__ fp16 g_Kf[MROWS*EMB];    // K fp16 [b,s,h,d]
__device__ fp16 g_Vf[MROWS*EMB];    // V fp16 [b,s,h,d]

// ---------------- helpers ------------------------------------------------------
__device__ __forceinline__ uint32_t smem_u32(const void* p) {
    return (uint32_t)__cvta_generic_to_shared(p);
}
__device__ __forceinline__ void cp_async16(uint32_t dst, const void* src) {
    asm volatile("cp.async.cg.shared.global [%0], [%1], 16;"
                 :: "r"(dst), "l"(src));
}
#define CP_COMMIT() asm volatile("cp.async.commit_group;" ::: "memory")
#define CP_WAIT1()  asm volatile("cp.async.wait_group 1;" ::: "memory")
#define CP_WAIT0()  asm volatile("cp.async.wait_group 0;" ::: "memory")

__device__ __forceinline__ void ldsm_x4(uint32_t& r0, uint32_t& r1, uint32_t& r2,
                                        uint32_t& r3, uint32_t addr) {
    asm volatile("ldmatrix.sync.aligned.m8n8.x4.shared.b16 {%0,%1,%2,%3}, [%4];"
                 : "=r"(r0), "=r"(r1), "=r"(r2), "=r"(r3) : "r"(addr));
}
__device__ __forceinline__ void ldsm_x2(uint32_t& r0, uint32_t& r1, uint32_t addr) {
    asm volatile("ldmatrix.sync.aligned.m8n8.x2.shared.b16 {%0,%1}, [%2];"
                 : "=r"(r0), "=r"(r1) : "r"(addr));
}
__device__ __forceinline__ void ldsm_x2t(uint32_t& r0, uint32_t& r1, uint32_t addr) {
    asm volatile("ldmatrix.sync.aligned.m8n8.x2.trans.shared.b16 {%0,%1}, [%2];"
                 : "=r"(r0), "=r"(r1) : "r"(addr));
}
__device__ __forceinline__ void mma_f16(float (&c)[4], const uint32_t (&a)[4],
                                        const uint32_t (&b)[2]) {
    asm volatile(
        "mma.sync.aligned.m16n8k16.row.col.f32.f16.f16.f32 "
        "{%0,%1,%2,%3}, {%4,%5,%6,%7}, {%8,%9}, {%0,%1,%2,%3};"
        : "+f"(c[0]), "+f"(c[1]), "+f"(c[2]), "+f"(c[3])
        : "r"(a[0]), "r"(a[1]), "r"(a[2]), "r"(a[3]), "r"(b[0]), "r"(b[1]));
}
__device__ __forceinline__ uint32_t pack2h(fp16 a, fp16 b) {
    __half2 t = __halves2half2(a, b);
    return *(uint32_t*)&t;
}
// single-instruction fp32x2 -> half2 pack
__device__ __forceinline__ uint32_t packf2(float a, float b) {
    __half2 t = __floats2half2_rn(a, b);
    return *(uint32_t*)&t;
}

// ---------------- cvt_all: all 7 fp32->fp16 conversions in one launch -------------
#define N4_IN (MROWS*EMB/4)    // 2097152
#define N4_W  (EMB*EMB/4)      // 262144
#define CVT_TOTAL (3*N4_IN + 4*N4_W)

__global__ __launch_bounds__(256)
void cvt_all(const float* __restrict__ q, const float* __restrict__ k,
             const float* __restrict__ v,
             const float* __restrict__ wq, const float* __restrict__ wk,
             const float* __restrict__ wv, const float* __restrict__ wo,
             fp16* __restrict__ A1, fp16* __restrict__ A2, fp16* __restrict__ A3,
             fp16* __restrict__ W1, fp16* __restrict__ W2, fp16* __restrict__ W3,
             fp16* __restrict__ W4) {
    int i = blockIdx.x * 256 + threadIdx.x;
    if (i >= CVT_TOTAL) return;
    const float* src;
    fp16* dst;
    if (i < 3 * N4_IN) {
        int job = i / N4_IN;
        i -= job * N4_IN;
        src = (job == 0) ? q : (job == 1) ? k : v;
        dst = (job == 0) ? A1 : (job == 1) ? A2 : A3;
    } else {
        int j = i - 3 * N4_IN;
        int job = j / N4_W;
        i = j - job * N4_W;
        src = (job == 0) ? wq : (job == 1) ? wk : (job == 2) ? wv : wo;
        dst = (job == 0) ? W1 : (job == 1) ? W2 : (job == 2) ? W3 : W4;
    }
    float4 vv = ((const float4*)src)[i];
    uint2 o;
    o.x = packf2(vv.x, vv.y);
    o.y = packf2(vv.z, vv.w);
    ((uint2*)dst)[i] = o;
}

// ---------------- GEMM body (fp16 mma, BK=64, cp.async 2-stage; R11 proven) -------
#define GROW 72               // smem row stride (halves): 64 + 8 pad
#define PL   (128*GROW)       // halves per plane (9216)
#define GSTG (2*PL)           // halves per stage (A + W)
#define GEMM_SMEM (2*GSTG*2)  // bytes = 73728

__device__ __forceinline__
void gemm_stage_load(const fp16* __restrict__ A, const fp16* __restrict__ W,
                     uint32_t smb, int stage, int m0, int n0, int k0, int K,
                     int tid) {
#pragma unroll
    for (int i = 0; i < 8; i++) {
        int idx = tid + i * 256;
        int pl = idx >> 10, rem = idx & 1023;
        int row = rem >> 3, c8 = (rem & 7) * 8;
        const fp16* src = pl ? W : A;
        int rb = pl ? n0 : m0;
        cp_async16(smb + (stage * GSTG + pl * PL + row * GROW + c8) * 2,
                   src + (size_t)(rb + row) * K + k0 + c8);
    }
    CP_COMMIT();
}

__device__ __forceinline__
void gemm_body(const fp16* __restrict__ A, const fp16* __restrict__ W,
               const float* __restrict__ bias,
               float* __restrict__ Cf, fp16* __restrict__ Ch,
               float oscale, int M, int N, int K, char* smraw) {
    const uint32_t smb = smem_u32(smraw);

    const int tid  = threadIdx.x;
    const int lane = tid & 31;
    const int wid  = tid >> 5;
    const int wm   = wid >> 2;
    const int wn   = wid & 3;
    const int m0 = blockIdx.y * 128;
    const int n0 = blockIdx.x * 128;

    float acc[4][4][4];
#pragma unroll
    for (int i = 0; i < 4; i++)
#pragma unroll
        for (int j = 0; j < 4; j++)
#pragma unroll
            for (int qq = 0; qq < 4; qq++) acc[i][j][qq] = 0.f;

    gemm_stage_load(A, W, smb, 0, m0, n0, 0, K, tid);

    const int NCH = K / 64;
    for (int ch = 0; ch < NCH; ch++) {
        const int buf = ch & 1;
        if (ch + 1 < NCH) {
            gemm_stage_load(A, W, smb, buf ^ 1, m0, n0, (ch + 1) * 64, K, tid);
            CP_WAIT1();
        } else {
            CP_WAIT0();
        }
        __syncthreads();

        const uint32_t bA = buf * GSTG;
#pragma unroll
        for (int kk = 0; kk < 4; kk++) {
            uint32_t af[4][4], bf[2][4];
#pragma unroll
            for (int mt = 0; mt < 4; mt++) {
                uint32_t off = (bA + (wm * 64 + mt * 16 + (lane & 15)) * GROW
                                + kk * 16 + (lane >> 4) * 8) * 2;
                ldsm_x4(af[mt][0], af[mt][1], af[mt][2], af[mt][3], smb + off);
            }
#pragma unroll
            for (int ntp = 0; ntp < 2; ntp++) {
                uint32_t off = (bA + PL + (wn * 32 + ntp * 16 + (lane & 15)) * GROW
                                + kk * 16 + (lane >> 4) * 8) * 2;
                ldsm_x4(bf[ntp][0], bf[ntp][1], bf[ntp][2], bf[ntp][3], smb + off);
            }
#pragma unroll
            for (int mt = 0; mt < 4; mt++)
#pragma unroll
                for (int nt = 0; nt < 4; nt++) {
                    uint32_t bb[2] = {bf[nt >> 1][nt & 1], bf[nt >> 1][(nt & 1) + 2]};
                    mma_f16(acc[mt][nt], af[mt], bb);
                }
        }
        __syncthreads();
    }

    // epilogue
#pragma unroll
    for (int nt = 0; nt < 4; nt++) {
        int n = n0 + wn * 32 + nt * 8 + (lane & 3) * 2;
        float b0 = bias[n], b1 = bias[n + 1];
#pragma unroll
        for (int mt = 0; mt < 4; mt++) {
            int m = m0 + wm * 64 + mt * 16 + (lane >> 2);
            float v00 = (acc[mt][nt][0] + b0) * oscale;
            float v01 = (acc[mt][nt][1] + b1) * oscale;
            float v10 = (acc[mt][nt][2] + b0) * oscale;
            float v11 = (acc[mt][nt][3] + b1) * oscale;
            size_t i0 = (size_t)m * N + n;
            size_t i1 = (size_t)(m + 8) * N + n;
            if (Cf) {
                *(float2*)&Cf[i0] = make_float2(v00, v01);
                *(float2*)&Cf[i1] = make_float2(v10, v11);
            }
            if (Ch) {
                *(uint32_t*)&Ch[i0] = packf2(v00, v01);
                *(uint32_t*)&Ch[i1] = packf2(v10, v11);
            }
        }
    }
}

// fused Q/K/V projections: blockIdx.z selects the job
__global__ __launch_bounds__(256, 2)
void gemm3_hmma(const fp16* __restrict__ A1, const fp16* __restrict__ W1,
                const float* __restrict__ bq, fp16* __restrict__ Qf,
                const fp16* __restrict__ A2, const fp16* __restrict__ W2,
                const float* __restrict__ bk, fp16* __restrict__ Kf,
                const fp16* __restrict__ A3, const fp16* __restrict__ W3,
                const float* __restrict__ bv, fp16* __restrict__ Vf) {
    extern __shared__ char sm[];
    int z = blockIdx.z;
    if (z == 0)
        gemm_body(A1, W1, bq, nullptr, Qf, 0.125f, MROWS, EMB, EMB, sm);
    else if (z == 1)
        gemm_body(A2, W2, bk, nullptr, Kf, 1.f, MROWS, EMB, EMB, sm);
    else
        gemm_body(A3, W3, bv, nullptr, Vf, 1.f, MROWS, EMB, EMB, sm);
}

// single GEMM (output projection)
__global__ __launch_bounds__(256, 2)
void gemm_hmma(const fp16* __restrict__ A, const fp16* __restrict__ W,
               const float* __restrict__ bias, float* __restrict__ Cf,
               float oscale, int M, int N, int K) {
    extern __shared__ char sm[];
    gemm_body(A, W, bias, Cf, nullptr, oscale, M, N, K, sm);
}

// ---------------- fused single-pass attention ---------------------------------------
#define QROWS 32
#define KCH   128
#define SROW  2056
#define KROWS 72
#define QROW  72
#define NTHR  512
#define A_S    0
#define S_BYTES (32*SROW*2)
#define A_U    S_BYTES
#define KPL    (KCH*KROWS*2)
#define STGB   (2*KPL)
#define A_QS   (A_U + 2*STGB)
#define A_RSUM (A_QS + 32*QROW*2)
#define ATTN_SMEM (A_RSUM + 256)

__global__ __launch_bounds__(NTHR, 1)
void attn_fused(const fp16* __restrict__ Qf, const fp16* __restrict__ Kf,
                const fp16* __restrict__ Vf,
                fp16* __restrict__ ctx, float* __restrict__ meanOut, int writeMean) {
    extern __shared__ char smem_raw[];
    fp16*  S      = (fp16*)(smem_raw + A_S);
    float* Sred   = (float*)(smem_raw + A_S);
    fp16*  Qs     = (fp16*)(smem_raw + A_QS);
    float* rowsum = (float*)(smem_raw + A_RSUM);

    const int b    = blockIdx.y;
    const int q0   = blockIdx.x * QROWS;
    const int tid  = threadIdx.x;
    const int lane = tid & 31;
    const int wid  = tid >> 5;
    const int rg   = wid >> 3;
    const int ks   = wid & 7;
    const float invH = 1.0f / HEADS;

    const uint32_t smb  = smem_u32(smem_raw);
    const uint32_t U_b  = smb + A_U;
    const uint32_t Qs_b = smb + A_QS;

    const fp16* KbB = Kf + (size_t)(b * SEQ) * EMB;
    const fp16* VbB = Vf + (size_t)(b * SEQ) * EMB;

    for (int h = 0; h < HEADS; h++) {
        if (tid < 32) rowsum[tid] = 0.f;
        {
            int row = tid >> 4, c4 = (tid & 15) * 4;
            size_t g = (size_t)(b * SEQ + q0 + row) * EMB + h * HDIM + c4;
            *(uint2*)&Qs[row * QROW + c4] = *(const uint2*)&Qf[g];
        }
        if (h == 0) {
#pragma unroll
            for (int i = 0; i < 4; i++) {
                int idx = tid + i * NTHR;
                int pl = idx >> 10, rem = idx & 1023;
                int row = rem >> 3, q8 = (rem & 7) * 8;
                const fp16* src = pl ? (VbB + h * HDIM) : (KbB + h * HDIM);
                cp_async16(U_b + pl * KPL + (row * KROWS + q8) * 2,
                           src + (size_t)row * EMB + q8);
            }
            CP_COMMIT();
        }
        __syncthreads();

        uint32_t Af[4][4];
#pragma unroll
        for (int ds = 0; ds < 4; ds++) {
            uint32_t off = ((rg * 16 + (lane & 15)) * QROW
                            + ds * 16 + (lane >> 4) * 8) * 2;
            ldsm_x4(Af[ds][0], Af[ds][1], Af[ds][2], Af[ds][3], Qs_b + off);
        }

        float out[8][4];
#pragma unroll
        for (int n8 = 0; n8 < 8; n8++)
#pragma unroll
            for (int qq = 0; qq < 4; qq++) out[n8][qq] = 0.f;
        float rs0 = 0.f, rs1 = 0.f;

        const fp16* Kb0 = KbB + h * HDIM;
        const fp16* Vb0 = VbB + h * HDIM;
        const int l = lane & 15;

        for (int ci = 0; ci < SEQ / KCH; ci++) {
            const int buf = ci & 1;
            if (ci + 1 < SEQ / KCH) {
                const int nb = buf ^ 1;
                const int kc2 = (ci + 1) * KCH;
#pragma unroll
                for (int i = 0; i < 4; i++) {
                    int idx = tid + i * NTHR;
                    int pl = idx >> 10, rem = idx & 1023;
                    int row = rem >> 3, q8 = (rem & 7) * 8;
                    const fp16* src = pl ? Vb0 : Kb0;
                    cp_async16(U_b + nb * STGB + pl * KPL + (row * KROWS + q8) * 2,
                               src + (size_t)(kc2 + row) * EMB + q8);
                }
                CP_COMMIT();
                CP_WAIT1();
            } else {
                CP_WAIT0();
            }
            __syncthreads();

            const uint32_t kb = U_b + buf * STGB;
            const uint32_t vb = kb + KPL;

            // ---- hoist V fragments (independent of scores/exp)
            uint32_t vfr[8][2];
#pragma unroll
            for (int n8 = 0; n8 < 8; n8++) {
                uint32_t boff = ((ks * 16 + l) * KROWS + n8 * 8) * 2;
                ldsm_x2t(vfr[n8][0], vfr[n8][1], vb + boff);
            }

            // ---- scores: two accumulator chains interleaved over ds
            float c0[4] = {0.f, 0.f, 0.f, 0.f};
            float c1[4] = {0.f, 0.f, 0.f, 0.f};
#pragma unroll
            for (int ds = 0; ds < 4; ds++) {
                uint32_t b0off = ((ks * 16 + (l & 7)) * KROWS
                                  + ds * 16 + ((l >> 3) & 1) * 8) * 2;
                uint32_t b1off = ((ks * 16 + 8 + (l & 7)) * KROWS
                                  + ds * 16 + ((l >> 3) & 1) * 8) * 2;
                uint32_t k0[2], k1[2];
                ldsm_x2(k0[0], k0[1], kb + b0off);
                ldsm_x2(k1[0], k1[1], kb + b1off);
                mma_f16(c0, Af[ds], k0);
                mma_f16(c1, Af[ds], k1);
            }

            // ---- exp via MUFU (frees the FMA pipe), rowsum, pack P
            float e0 = __expf(c0[0]);
            float e1 = __expf(c0[1]);
            float e2 = __expf(c0[2]);
            float e3 = __expf(c0[3]);
            float e4 = __expf(c1[0]);
            float e5 = __expf(c1[1]);
            float e6 = __expf(c1[2]);
            float e7 = __expf(c1[3]);
            rs0 += (e0 + e1) + (e4 + e5);
            rs1 += (e2 + e3) + (e6 + e7);
            uint32_t pa[4];
            pa[0] = packf2(e0, e1);
            pa[1] = packf2(e2, e3);
            pa[2] = packf2(e4, e5);
            pa[3] = packf2(e6, e7);

            // ---- PV with pre-loaded V fragments
#pragma unroll
            for (int n8 = 0; n8 < 8; n8++)
                mma_f16(out[n8], pa, vfr[n8]);

            // ---- S stores (off critical path)
            {
                int row0 = rg * 16 + (lane >> 2);
                int col  = ci * KCH + ks * 16 + (lane & 3) * 2;
                *(uint32_t*)&S[row0 * SROW + col]           = pa[0];
                *(uint32_t*)&S[(row0 + 8) * SROW + col]     = pa[1];
                *(uint32_t*)&S[row0 * SROW + col + 8]       = pa[2];
                *(uint32_t*)&S[(row0 + 8) * SROW + col + 8] = pa[3];
            }
            __syncthreads();
        }

        if (h + 1 < HEADS) {
            const fp16* Kn = KbB + (h + 1) * HDIM;
            const fp16* Vn = VbB + (h + 1) * HDIM;
#pragma unroll
            for (int i = 0; i < 4; i++) {
                int idx = tid + i * NTHR;
                int pl = idx >> 10, rem = idx & 1023;
                int row = rem >> 3, q8 = (rem & 7) * 8;
                const fp16* src = pl ? Vn : Kn;
                cp_async16(U_b + pl * KPL + (row * KROWS + q8) * 2,
                           src + (size_t)row * EMB + q8);
            }
            CP_COMMIT();
        }

        rs0 += __shfl_xor_sync(0xffffffffu, rs0, 1);
        rs0 += __shfl_xor_sync(0xffffffffu, rs0, 2);
        rs1 += __shfl_xor_sync(0xffffffffu, rs1, 1);
        rs1 += __shfl_xor_sync(0xffffffffu, rs1, 2);
        if ((lane & 3) == 0) {
            int r = rg * 16 + (lane >> 2);
            atomicAdd(&rowsum[r], rs0);
            atomicAdd(&rowsum[r + 8], rs1);
        }
        __syncthreads();

        if (writeMean) {
#pragma unroll
            for (int rr = 0; rr < 2; rr++) {
                const int r = wid * 2 + rr;
                float fac = invH / rowsum[r];
                float* mrow = meanOut + ((size_t)b * SEQ + q0 + r) * SEQ;
#pragma unroll
                for (int it = 0; it < 8; it++) {
                    int base = it * 256 + lane * 8;
                    uint4 hv = *(uint4*)&S[r * SROW + base];
                    __half2* hp = (__half2*)&hv;
                    float e[8];
#pragma unroll
                    for (int p = 0; p < 4; p++) {
                        float2 f = __half22float2(hp[p]);
                        e[p * 2]     = f.x;
                        e[p * 2 + 1] = f.y;
                    }
                    if (h == 0) {
                        float4 m0 = make_float4(e[0] * fac, e[1] * fac,
                                                e[2] * fac, e[3] * fac);
                        float4 m1 = make_float4(e[4] * fac, e[5] * fac,
                                                e[6] * fac, e[7] * fac);
                        *(float4*)&mrow[base]     = m0;
                        *(float4*)&mrow[base + 4] = m1;
                    } else {
                        float4 m0 = *(const float4*)&mrow[base];
                        float4 m1 = *(const float4*)&mrow[base + 4];
                        m0.x = fmaf(e[0], fac, m0.x); m0.y = fmaf(e[1], fac, m0.y);
                        m0.z = fmaf(e[2], fac, m0.z); m0.w = fmaf(e[3], fac, m0.w);
                        m1.x = fmaf(e[4], fac, m1.x); m1.y = fmaf(e[5], fac, m1.y);
                        m1.z = fmaf(e[6], fac, m1.z); m1.w = fmaf(e[7], fac, m1.w);
                        *(float4*)&mrow[base]     = m0;
                        *(float4*)&mrow[base + 4] = m1;
                    }
                }
            }
        }
        __syncthreads();

        {
            float* dst = Sred + wid * 1024;
            int rl = lane >> 2, cl = (lane & 3) * 2;
#pragma unroll
            for (int n8 = 0; n8 < 8; n8++) {
                *(float2*)&dst[rl * 64 + n8 * 8 + cl]       =
                    make_float2(out[n8][0], out[n8][1]);
                *(float2*)&dst[(rl + 8) * 64 + n8 * 8 + cl] =
                    make_float2(out[n8][2], out[n8][3]);
            }
        }
        __syncthreads();

        {
            int row = tid >> 4;
            int col = (tid & 15) * 4;
            float s4[4] = {0.f, 0.f, 0.f, 0.f};
            int wbase = (row >> 4) * 8;
            int off   = (row & 15) * 64 + col;
#pragma unroll
            for (int w = 0; w < 8; w++) {
                const float* src = Sred + (wbase + w) * 1024 + off;
                s4[0] += src[0]; s4[1] += src[1];
                s4[2] += src[2]; s4[3] += src[3];
            }
            float inv = __fdividef(1.f, rowsum[row]);
            uint2 o;
            o.x = packf2(s4[0] * inv, s4[1] * inv);
            o.y = packf2(s4[2] * inv, s4[3] * inv);
            *(uint2*)&ctx[(size_t)(b * SEQ + q0 + row) * EMB + h * HDIM + col] = o;
        }
        __syncthreads();
    }
}

// ---------------- launch ------------------------------------------------------------
extern "C" void kernel_launch(void* const* d_in, const int* in_sizes, int n_in,
                              void* d_out, int out_size) {
    const float* query = (const float*)d_in[0];
    const float* key_  = (const float*)d_in[1];
    const float* value = (const float*)d_in[2];
    const float* Wq = (const float*)d_in[3];
    const float* bq = (const float*)d_in[4];
    const float* Wk = (const float*)d_in[5];
    const float* bk = (const float*)d_in[6];
    const float* Wv = (const float*)d_in[7];
    const float* bv = (const float*)d_in[8];
    const float* Wo = (const float*)d_in[9];
    const float* bo = (const float*)d_in[10];

    float* out = (float*)d_out;
    const size_t outElems  = (size_t)MROWS * EMB;
    const size_t meanElems = (size_t)BATCH * SEQ * SEQ;
    int writeMean = ((size_t)out_size >= outElems + meanElems) ? 1 : 0;
    float* meanOut = out + outElems;

    fp16 *A1, *A2, *A3, *W1, *W2, *W3, *W4, *Qfb, *Kfb, *Vfb;
    cudaGetSymbolAddress((void**)&A1,  g_A1);
    cudaGetSymbolAddress((void**)&A2,  g_A2);
    cudaGetSymbolAddress((void**)&A3,  g_A3);
    cudaGetSymbolAddress((void**)&W1,  g_W1);
    cudaGetSymbolAddress((void**)&W2,  g_W2);
    cudaGetSymbolAddress((void**)&W3,  g_W3);
    cudaGetSymbolAddress((void**)&W4,  g_W4);
    cudaGetSymbolAddress((void**)&Qfb, g_Qf);
    cudaGetSymbolAddress((void**)&Kfb, g_Kf);
    cudaGetSymbolAddress((void**)&Vfb, g_Vf);

    cudaFuncSetAttribute(gemm3_hmma, cudaFuncAttributeMaxDynamicSharedMemorySize,
                         GEMM_SMEM);
    cudaFuncSetAttribute(gemm_hmma, cudaFuncAttributeMaxDynamicSharedMemorySize,
                         GEMM_SMEM);
    cudaFuncSetAttribute(attn_fused, cudaFuncAttributeMaxDynamicSharedMemorySize,
                         ATTN_SMEM);

    // 1) all conversions (7 jobs, one launch)
    cvt_all<<<(CVT_TOTAL + 255) / 256, 256>>>(
        query, key_, value, Wq, Wk, Wv, Wo,
        A1, A2, A3, W1, W2, W3, W4);

    // 2) Q/K/V projections fused in one grid (z = job)
    gemm3_hmma<<<dim3(EMB / 128, MROWS / 128, 3), 256, GEMM_SMEM>>>(
        A1, W1, bq, Qfb,
        A2, W2, bk, Kfb,
        A3, W3, bv, Vfb);

    // 3) fused attention -> ctx fp16 into A1
    attn_fused<<<dim3(SEQ / QROWS, BATCH), NTHR, ATTN_SMEM>>>(
        Qfb, Kfb, Vfb, A1, meanOut, writeMean);

    // 4) output projection -> fp32 out
    gemm_hmma<<<dim3(EMB / 128, MROWS / 128), 256, GEMM_SMEM>>>(
        A1, W4, bo, out, 1.f, MROWS, EMB, EMB);
}